// round 5
// baseline (speedup 1.0000x reference)
#include <cuda_runtime.h>
#include <float.h>
#include <stdint.h>

#define B_   4
#define N_   2048
#define DIM_ 256
#define H_   8
#define HD_  32
#define M_   4
#define S_   2052          // N + M
#define TOPK_ 32
#define ROWS_ (B_*N_)      // 8192

#define QT_  8             // queries per block (attention)
#define KT_  128           // keys per shared tile
#define SP_  2056          // padded score row stride
#define KSTR_ 36           // padded K-tile row stride (floats)

// ---------------- scratch (no cudaMalloc allowed) ----------------
__device__ float g_q[B_*H_*N_*HD_];      // 8 MB
__device__ float g_k[B_*H_*N_*HD_];      // 8 MB
__device__ float g_v[B_*H_*N_*HD_];      // 8 MB
__device__ float g_attn[B_*N_*H_*HD_];   // 8 MB  [B,N,H*HD]

// monotonic float -> uint mapping (order-preserving, bijective)
__device__ __forceinline__ unsigned enc_f(float f) {
    unsigned u = __float_as_uint(f);
    return u ^ ((u & 0x80000000u) ? 0xFFFFFFFFu : 0x80000000u);
}

// =====================================================================
// GEMM 1: qkv = x @ w_qkv + b_qkv, scattered into g_q/g_k/g_v [B,H,N,HD]
// =====================================================================
__global__ __launch_bounds__(256) void gemm_qkv_kernel(
    const float* __restrict__ X, const float* __restrict__ W,
    const float* __restrict__ bias)
{
    __shared__ __align__(16) float As[16 * 132];   // [k][m], padded
    __shared__ __align__(16) float Bs[16 * 128];   // [k][n]
    const int tid = threadIdx.x;
    const int rowBase = blockIdx.y * 128;
    const int colBase = blockIdx.x * 128;
    const int ty = tid >> 4, tx = tid & 15;

    float acc[8][8];
#pragma unroll
    for (int i = 0; i < 8; i++)
#pragma unroll
        for (int j = 0; j < 8; j++) acc[i][j] = 0.f;

    for (int kb = 0; kb < DIM_; kb += 16) {
#pragma unroll
        for (int i = 0; i < 2; i++) {
            int f4 = tid + i * 256;
            int row = f4 >> 2;
            int kc = (f4 & 3) << 2;
            float4 v = *reinterpret_cast<const float4*>(
                X + (size_t)(rowBase + row) * DIM_ + kb + kc);
            As[(kc + 0) * 132 + row] = v.x;
            As[(kc + 1) * 132 + row] = v.y;
            As[(kc + 2) * 132 + row] = v.z;
            As[(kc + 3) * 132 + row] = v.w;
        }
#pragma unroll
        for (int i = 0; i < 2; i++) {
            int f4 = tid + i * 256;
            int kr = f4 >> 5;
            int cc = (f4 & 31) << 2;
            *reinterpret_cast<float4*>(&Bs[kr * 128 + cc]) =
                *reinterpret_cast<const float4*>(
                    W + (size_t)(kb + kr) * 768 + colBase + cc);
        }
        __syncthreads();
#pragma unroll
        for (int kk = 0; kk < 16; kk++) {
            float a[8], b[8];
            *reinterpret_cast<float4*>(&a[0]) =
                *reinterpret_cast<const float4*>(&As[kk * 132 + ty * 8]);
            *reinterpret_cast<float4*>(&a[4]) =
                *reinterpret_cast<const float4*>(&As[kk * 132 + ty * 8 + 4]);
            *reinterpret_cast<float4*>(&b[0]) =
                *reinterpret_cast<const float4*>(&Bs[kk * 128 + tx * 8]);
            *reinterpret_cast<float4*>(&b[4]) =
                *reinterpret_cast<const float4*>(&Bs[kk * 128 + tx * 8 + 4]);
#pragma unroll
            for (int i = 0; i < 8; i++)
#pragma unroll
                for (int j = 0; j < 8; j++) acc[i][j] += a[i] * b[j];
        }
        __syncthreads();
    }

#pragma unroll
    for (int i = 0; i < 8; i++) {
        int r = rowBase + ty * 8 + i;
        int bb = r >> 11;
        int n = r & (N_ - 1);
#pragma unroll
        for (int j = 0; j < 8; j++) {
            int c = colBase + tx * 8 + j;
            float val = acc[i][j] + bias[c];
            int t = c >> 8;
            int h = (c >> 5) & 7;
            int d = c & 31;
            float* dst = (t == 0) ? g_q : (t == 1) ? g_k : g_v;
            dst[(((size_t)(bb * H_ + h)) * N_ + n) * HD_ + d] = val;
        }
    }
}

// =====================================================================
// Attention: one block = 8 queries of one (b,h). 256 threads.
// Phase 1 (GEMM-style): scores[8][2052] into dyn smem via shared K tiles.
// Phase 2 (warp per query): exact radix select with match_any-dedup'd
//   histograms (no serialized atomics) -> fused softmax + sparse AV.
// =====================================================================
__global__ __launch_bounds__(256, 2) void attn_kernel(
    const float* __restrict__ scale,
    const float* __restrict__ mem_k,
    const float* __restrict__ mem_v)
{
    extern __shared__ __align__(16) float smem[];
    float*    sc    = smem;                       // [QT][SP_]      65792 B
    float*    qsh   = sc + QT_ * SP_;             // [QT][32]        1024 B
    float*    ktile = qsh + QT_ * 32;             // [KT][KSTR_]    18432 B
    unsigned* hist  = (unsigned*)(ktile + KT_ * KSTR_); // [QT][256]  8192 B

    const int tid = threadIdx.x;
    const int bid = blockIdx.x;
    const int qt = bid & 255;              // N_/QT_ = 256 tiles
    const int h  = (bid >> 8) & (H_ - 1);
    const int b  = bid >> 11;
    const int n0 = qt * QT_;

    const float sfac = 0.17677669529663687f * scale[h];
    const float* kbase = g_k + ((size_t)(b * H_ + h)) * N_ * HD_;
    const float* vbase = g_v + ((size_t)(b * H_ + h)) * N_ * HD_;

    // load 8 q rows (contiguous 256 floats)
    {
        const float* qb = g_q + (((size_t)(b * H_ + h)) * N_ + n0) * HD_;
        if (tid < QT_ * HD_) qsh[tid] = qb[tid];
    }

    // ---------- Phase 1: scores ----------
    const int key = tid & 127;             // key within tile
    const int qg  = tid >> 7;              // query group 0/1 -> queries qg*4..+3
    for (int tile = 0; tile < (S_ + KT_ - 1) / KT_; tile++) {
        const int base = tile * KT_;
#pragma unroll
        for (int i = 0; i < 4; i++) {
            int f4 = tid + i * 256;        // 0..1023
            int kk = f4 >> 3;
            int k4 = f4 & 7;
            int s = base + kk;
            float4 v = make_float4(0.f, 0.f, 0.f, 0.f);
            if (s < N_)
                v = *reinterpret_cast<const float4*>(kbase + (size_t)s * HD_ + k4 * 4);
            else if (s < S_)
                v = *reinterpret_cast<const float4*>(mem_k + (h * M_ + (s - N_)) * HD_ + k4 * 4);
            *reinterpret_cast<float4*>(&ktile[kk * KSTR_ + k4 * 4]) = v;
        }
        __syncthreads();

        float acc0 = 0.f, acc1 = 0.f, acc2 = 0.f, acc3 = 0.f;
#pragma unroll
        for (int j = 0; j < 8; j++) {
            float4 kv = *reinterpret_cast<const float4*>(&ktile[key * KSTR_ + j * 4]);
            float4 q0 = *reinterpret_cast<const float4*>(&qsh[(qg * 4 + 0) * 32 + j * 4]);
            float4 q1 = *reinterpret_cast<const float4*>(&qsh[(qg * 4 + 1) * 32 + j * 4]);
            float4 q2 = *reinterpret_cast<const float4*>(&qsh[(qg * 4 + 2) * 32 + j * 4]);
            float4 q3 = *reinterpret_cast<const float4*>(&qsh[(qg * 4 + 3) * 32 + j * 4]);
            acc0 += q0.x*kv.x + q0.y*kv.y + q0.z*kv.z + q0.w*kv.w;
            acc1 += q1.x*kv.x + q1.y*kv.y + q1.z*kv.z + q1.w*kv.w;
            acc2 += q2.x*kv.x + q2.y*kv.y + q2.z*kv.z + q2.w*kv.w;
            acc3 += q3.x*kv.x + q3.y*kv.y + q3.z*kv.z + q3.w*kv.w;
        }
        const int s = base + key;
        if (s < S_) {
            float r0 = acc0 * sfac, r1 = acc1 * sfac, r2 = acc2 * sfac, r3 = acc3 * sfac;
            if (s == n0 + qg * 4 + 0) r0 = -FLT_MAX;
            if (s == n0 + qg * 4 + 1) r1 = -FLT_MAX;
            if (s == n0 + qg * 4 + 2) r2 = -FLT_MAX;
            if (s == n0 + qg * 4 + 3) r3 = -FLT_MAX;
            sc[(qg * 4 + 0) * SP_ + s] = r0;
            sc[(qg * 4 + 1) * SP_ + s] = r1;
            sc[(qg * 4 + 2) * SP_ + s] = r2;
            sc[(qg * 4 + 3) * SP_ + s] = r3;
        }
        __syncthreads();
    }

    // ---------- Phase 2: one warp per query ----------
    const int wid  = tid >> 5;             // query index 0..7
    const int lane = tid & 31;
    float* row = sc + wid * SP_;
    unsigned* h8 = hist + wid * 256;

    unsigned prefix = 0, rem = TOPK_;
    float rowmax = -FLT_MAX;
    const int FULL = S_ / 32;              // 64 full warp iterations

    // ---- pass 3: top byte over full row (match_any dedup, track rowmax) ----
    for (int i = lane; i < 256; i += 32) h8[i] = 0u;
    __syncwarp();
    for (int it = 0; it < FULL; it++) {
        float val = row[it * 32 + lane];
        rowmax = fmaxf(rowmax, val);
        unsigned byte = enc_f(val) >> 24;
        unsigned grp = __match_any_sync(0xffffffffu, byte);
        if (lane == __ffs(grp) - 1) atomicAdd(&h8[byte], __popc(grp));
    }
    {   // tail (lanes 0..3 valid)
        int s = FULL * 32 + lane;
        bool v = s < S_;
        float val = v ? row[s] : 0.f;
        if (v) rowmax = fmaxf(rowmax, val);
        unsigned byte = v ? (enc_f(val) >> 24) : 0u;
        unsigned valid = __ballot_sync(0xffffffffu, v);
        unsigned grp = __match_any_sync(0xffffffffu, byte);
        unsigned c = __popc(grp & valid);
        if (lane == (unsigned)(__ffs(grp) - 1) && c) atomicAdd(&h8[byte], c);
    }
    __syncwarp();

    // select + remaining passes
    for (int pass = 3; pass >= 0; --pass) {
        // ---- select bin containing the rem-th largest ----
        unsigned c8[8], lsum = 0;
#pragma unroll
        for (int j = 0; j < 8; j++) { c8[j] = h8[lane * 8 + j]; lsum += c8[j]; }
        unsigned acc = lsum;
#pragma unroll
        for (int o = 1; o < 32; o <<= 1) {
            unsigned other = __shfl_down_sync(0xffffffffu, acc, o);
            if (lane + o < 32) acc += other;
        }
        unsigned run = acc - lsum;
        int sel = -1; unsigned newrem = 0;
#pragma unroll
        for (int j = 7; j >= 0; j--) {
            unsigned prev = run;
            run += c8[j];
            if (sel < 0 && run >= rem && prev < rem) {
                sel = lane * 8 + j;
                newrem = rem - prev;
            }
        }
        unsigned bal = __ballot_sync(0xffffffffu, sel >= 0);
        int src = __ffs(bal) - 1;
        sel    = __shfl_sync(0xffffffffu, sel, src);
        newrem = __shfl_sync(0xffffffffu, newrem, src);
        prefix |= ((unsigned)sel) << (pass * 8);
        rem = newrem;
        if (pass == 0) break;

        // ---- histogram of next byte, filtered by running prefix ----
        const int shift = (pass - 1) * 8;
        const unsigned hi = prefix >> (shift + 8);
        for (int i = lane; i < 256; i += 32) h8[i] = 0u;
        __syncwarp();
        for (int it = 0; it <= FULL; it++) {
            int s = it * 32 + lane;
            bool v = s < S_;
            unsigned k = v ? enc_f(row[s]) : 0u;
            bool p = v && ((k >> (shift + 8)) == hi);
            unsigned pb = __ballot_sync(0xffffffffu, p);
            if (!pb) continue;              // common fast path: no candidates here
            unsigned byte = p ? ((k >> shift) & 255u) : 0u;
            unsigned grp = __match_any_sync(0xffffffffu, byte);
            unsigned c = __popc(grp & pb);
            if (lane == (unsigned)(__ffs(grp) - 1) && c) atomicAdd(&h8[byte], c);
        }
        __syncwarp();
    }
    // warp-reduce rowmax
#pragma unroll
    for (int o = 16; o; o >>= 1)
        rowmax = fmaxf(rowmax, __shfl_xor_sync(0xffffffffu, rowmax, o));
    const unsigned uthr = prefix;          // exact key of kth largest

    // ---- fused softmax + sparse AV (survivors via ballot; coalesced V) ----
    float accv = 0.f, wsum = 0.f;
    for (int s0 = 0; s0 < S_; s0 += 32) {
        const int s = s0 + lane;
        bool p = false; float w = 0.f;
        if (s < S_) {
            float v = row[s];
            if (enc_f(v) >= uthr) { p = true; w = __expf(v - rowmax); }
        }
        unsigned m = __ballot_sync(0xffffffffu, p);
        while (m) {
            int l = __ffs(m) - 1;
            m &= m - 1;
            int ss = s0 + l;
            float ww = __shfl_sync(0xffffffffu, w, l);
            wsum += ww;
            const float* vp = (ss < N_) ? (vbase + (size_t)ss * HD_)
                                        : (mem_v + (h * M_ + (ss - N_)) * HD_);
            accv += ww * vp[lane];
        }
    }
    g_attn[((size_t)(b * N_ + n0 + wid)) * (H_ * HD_) + h * HD_ + lane] = accv / wsum;
}

// =====================================================================
// GEMM 2: out = g_attn @ w_proj + b_proj.  [8192,256] x [256,256]
// =====================================================================
__global__ __launch_bounds__(256) void gemm_proj_kernel(
    const float* __restrict__ W, const float* __restrict__ bias,
    float* __restrict__ out)
{
    __shared__ __align__(16) float As[16 * 132];
    __shared__ __align__(16) float Bs[16 * 128];
    const int tid = threadIdx.x;
    const int rowBase = blockIdx.y * 128;
    const int colBase = blockIdx.x * 128;
    const int ty = tid >> 4, tx = tid & 15;

    float acc[8][8];
#pragma unroll
    for (int i = 0; i < 8; i++)
#pragma unroll
        for (int j = 0; j < 8; j++) acc[i][j] = 0.f;

    for (int kb = 0; kb < 256; kb += 16) {
#pragma unroll
        for (int i = 0; i < 2; i++) {
            int f4 = tid + i * 256;
            int row = f4 >> 2;
            int kc = (f4 & 3) << 2;
            float4 v = *reinterpret_cast<const float4*>(
                g_attn + (size_t)(rowBase + row) * 256 + kb + kc);
            As[(kc + 0) * 132 + row] = v.x;
            As[(kc + 1) * 132 + row] = v.y;
            As[(kc + 2) * 132 + row] = v.z;
            As[(kc + 3) * 132 + row] = v.w;
        }
#pragma unroll
        for (int i = 0; i < 2; i++) {
            int f4 = tid + i * 256;
            int kr = f4 >> 5;
            int cc = (f4 & 31) << 2;
            *reinterpret_cast<float4*>(&Bs[kr * 128 + cc]) =
                *reinterpret_cast<const float4*>(
                    W + (size_t)(kb + kr) * 256 + colBase + cc);
        }
        __syncthreads();
#pragma unroll
        for (int kk = 0; kk < 16; kk++) {
            float a[8], b[8];
            *reinterpret_cast<float4*>(&a[0]) =
                *reinterpret_cast<const float4*>(&As[kk * 132 + ty * 8]);
            *reinterpret_cast<float4*>(&a[4]) =
                *reinterpret_cast<const float4*>(&As[kk * 132 + ty * 8 + 4]);
            *reinterpret_cast<float4*>(&b[0]) =
                *reinterpret_cast<const float4*>(&Bs[kk * 128 + tx * 8]);
            *reinterpret_cast<float4*>(&b[4]) =
                *reinterpret_cast<const float4*>(&Bs[kk * 128 + tx * 8 + 4]);
#pragma unroll
            for (int i = 0; i < 8; i++)
#pragma unroll
                for (int j = 0; j < 8; j++) acc[i][j] += a[i] * b[j];
        }
        __syncthreads();
    }

#pragma unroll
    for (int i = 0; i < 8; i++) {
        int r = rowBase + ty * 8 + i;
#pragma unroll
        for (int j = 0; j < 8; j++) {
            int c = colBase + tx * 8 + j;
            out[(size_t)r * 256 + c] = acc[i][j] + bias[c];
        }
    }
}

// =====================================================================
extern "C" void kernel_launch(void* const* d_in, const int* in_sizes, int n_in,
                              void* d_out, int out_size)
{
    const float* x      = (const float*)d_in[0];
    const float* w_qkv  = (const float*)d_in[1];
    const float* b_qkv  = (const float*)d_in[2];
    const float* w_proj = (const float*)d_in[3];
    const float* b_proj = (const float*)d_in[4];
    const float* scale  = (const float*)d_in[5];
    const float* mem_k  = (const float*)d_in[6];
    const float* mem_v  = (const float*)d_in[7];
    float* out = (float*)d_out;

    dim3 g1(768 / 128, ROWS_ / 128);
    gemm_qkv_kernel<<<g1, 256>>>(x, w_qkv, b_qkv);

    const int smem_bytes = (QT_ * SP_ + QT_ * 32 + KT_ * KSTR_) * 4 + QT_ * 256 * 4;
    static int attr_set = 0;
    if (!attr_set) {
        cudaFuncSetAttribute(attn_kernel,
                             cudaFuncAttributeMaxDynamicSharedMemorySize, smem_bytes);
        attr_set = 1;
    }
    attn_kernel<<<B_ * H_ * (N_ / QT_), 256, smem_bytes>>>(scale, mem_k, mem_v);

    dim3 g3(256 / 128, ROWS_ / 128);
    gemm_proj_kernel<<<g3, 256>>>(w_proj, b_proj, out);
}

// round 7
// speedup vs baseline: 1.1814x; 1.1814x over previous
#include <cuda_runtime.h>
#include <float.h>
#include <stdint.h>

#define B_   4
#define N_   2048
#define DIM_ 256
#define H_   8
#define HD_  32
#define M_   4
#define S_   2052          // N + M
#define TOPK_ 32
#define ROWS_ (B_*N_)      // 8192

#define QT_   16           // queries per block (attention)
#define KT_   128          // keys per shared tile
#define SP_   2052         // score row stride (floats)
#define KSTR_ 36           // padded K-tile row stride (floats)
#define NTILE_ 17          // ceil(S_/KT_)
#define AVCAP_ 128         // batched-AV survivor capacity per query

typedef unsigned long long ull;

// ---------------- scratch (no cudaMalloc allowed) ----------------
__device__ float g_q[B_*H_*N_*HD_];      // 8 MB
__device__ float g_k[B_*H_*N_*HD_];      // 8 MB
__device__ float g_v[B_*H_*N_*HD_];      // 8 MB
__device__ float g_attn[B_*N_*H_*HD_];   // 8 MB  [B,N,H*HD]

__device__ __forceinline__ ull pk2(float a, float b) {
    ull r; asm("mov.b64 %0, {%1,%2};" : "=l"(r) : "f"(a), "f"(b)); return r;
}
__device__ __forceinline__ void fma2(ull& d, ull a, ull b) {
    asm("fma.rn.f32x2 %0, %1, %2, %0;" : "+l"(d) : "l"(a), "l"(b));
}
__device__ __forceinline__ float upk_sum(ull a) {
    float lo, hi; asm("mov.b64 {%0,%1}, %2;" : "=f"(lo), "=f"(hi) : "l"(a));
    return lo + hi;
}
__device__ __forceinline__ float warp_min(float v) {
#pragma unroll
    for (int o = 16; o; o >>= 1) v = fminf(v, __shfl_xor_sync(0xffffffffu, v, o));
    return v;
}

// =====================================================================
// GEMM 1: qkv = x @ w_qkv + b_qkv, scattered into g_q/g_k/g_v [B,H,N,HD]
// =====================================================================
__global__ __launch_bounds__(256) void gemm_qkv_kernel(
    const float* __restrict__ X, const float* __restrict__ W,
    const float* __restrict__ bias)
{
    __shared__ __align__(16) float As[16 * 132];   // [k][m], padded
    __shared__ __align__(16) float Bs[16 * 128];   // [k][n]
    const int tid = threadIdx.x;
    const int rowBase = blockIdx.y * 128;
    const int colBase = blockIdx.x * 128;
    const int ty = tid >> 4, tx = tid & 15;

    float acc[8][8];
#pragma unroll
    for (int i = 0; i < 8; i++)
#pragma unroll
        for (int j = 0; j < 8; j++) acc[i][j] = 0.f;

    for (int kb = 0; kb < DIM_; kb += 16) {
#pragma unroll
        for (int i = 0; i < 2; i++) {
            int f4 = tid + i * 256;
            int row = f4 >> 2;
            int kc = (f4 & 3) << 2;
            float4 v = *reinterpret_cast<const float4*>(
                X + (size_t)(rowBase + row) * DIM_ + kb + kc);
            As[(kc + 0) * 132 + row] = v.x;
            As[(kc + 1) * 132 + row] = v.y;
            As[(kc + 2) * 132 + row] = v.z;
            As[(kc + 3) * 132 + row] = v.w;
        }
#pragma unroll
        for (int i = 0; i < 2; i++) {
            int f4 = tid + i * 256;
            int kr = f4 >> 5;
            int cc = (f4 & 31) << 2;
            *reinterpret_cast<float4*>(&Bs[kr * 128 + cc]) =
                *reinterpret_cast<const float4*>(
                    W + (size_t)(kb + kr) * 768 + colBase + cc);
        }
        __syncthreads();
#pragma unroll
        for (int kk = 0; kk < 16; kk++) {
            float a[8], b[8];
            *reinterpret_cast<float4*>(&a[0]) =
                *reinterpret_cast<const float4*>(&As[kk * 132 + ty * 8]);
            *reinterpret_cast<float4*>(&a[4]) =
                *reinterpret_cast<const float4*>(&As[kk * 132 + ty * 8 + 4]);
            *reinterpret_cast<float4*>(&b[0]) =
                *reinterpret_cast<const float4*>(&Bs[kk * 128 + tx * 8]);
            *reinterpret_cast<float4*>(&b[4]) =
                *reinterpret_cast<const float4*>(&Bs[kk * 128 + tx * 8 + 4]);
#pragma unroll
            for (int i = 0; i < 8; i++)
#pragma unroll
                for (int j = 0; j < 8; j++) acc[i][j] += a[i] * b[j];
        }
        __syncthreads();
    }

#pragma unroll
    for (int i = 0; i < 8; i++) {
        int r = rowBase + ty * 8 + i;
        int bb = r >> 11;
        int n = r & (N_ - 1);
#pragma unroll
        for (int j = 0; j < 8; j++) {
            int c = colBase + tx * 8 + j;
            float val = acc[i][j] + bias[c];
            int t = c >> 8;
            int h = (c >> 5) & 7;
            int d = c & 31;
            float* dst = (t == 0) ? g_q : (t == 1) ? g_k : g_v;
            dst[(((size_t)(bb * H_ + h)) * N_ + n) * HD_ + d] = val;
        }
    }
}

// =====================================================================
// Attention: one block = 16 queries of one (b,h). 512 threads, 16 warps.
// Phase 1: scores[16][2052] via shared K tiles (reg-prefetch double buf,
//          packed f32x2 FMAs).
// Phase 2: warp per query: streaming register top-32 (exact, no atomics)
//          -> survivor compaction -> batched sparse AV.
// =====================================================================
__global__ __launch_bounds__(512, 1) void attn_kernel(
    const float* __restrict__ scale,
    const float* __restrict__ mem_k,
    const float* __restrict__ mem_v)
{
    extern __shared__ __align__(16) float smem[];
    float* sc    = smem;                    // [QT][SP]     131328 B
    float* qsh   = sc + QT_ * SP_;          // [QT][32]       2048 B
    float* ktile = qsh + QT_ * 32;          // [KT][KSTR_]   18432 B

    const int tid = threadIdx.x;
    const int bid = blockIdx.x;
    const int qt = bid & 127;               // N_/QT_ = 128 tiles
    const int h  = (bid >> 7) & (H_ - 1);
    const int b  = bid >> 10;
    const int n0 = qt * QT_;

    const float sfac = 0.17677669529663687f * scale[h];
    const float* kbase = g_k + ((size_t)(b * H_ + h)) * N_ * HD_;
    const float* vbase = g_v + ((size_t)(b * H_ + h)) * N_ * HD_;

    // load 16 q rows (contiguous 512 floats)
    {
        const float* qb = g_q + (((size_t)(b * H_ + h)) * N_ + n0) * HD_;
        qsh[tid] = qb[tid];
    }

    // staging geometry: 1024 float4 per tile / 512 threads = 2 each
    const int kk0 = tid >> 3, k40 = tid & 7;              // item 0
    const int kk1 = (tid + 512) >> 3, k41 = tid & 7;      // item 1
    float4 pre0, pre1;
    {   // prefetch tile 0
        int s0 = kk0, s1 = kk1;
        const float* p0 = (s0 < N_) ? kbase + (size_t)s0 * HD_ + k40 * 4
                                    : mem_k + (h * M_ + (s0 - N_)) * HD_ + k40 * 4;
        const float* p1 = (s1 < N_) ? kbase + (size_t)s1 * HD_ + k41 * 4
                                    : mem_k + (h * M_ + (s1 - N_)) * HD_ + k41 * 4;
        pre0 = *reinterpret_cast<const float4*>(p0);
        pre1 = *reinterpret_cast<const float4*>(p1);
    }

    const int key = tid & 127;
    const int qbase = (tid >> 7) * 4;       // query group base (0,4,8,12)

    // ---------- Phase 1: scores ----------
    for (int tile = 0; tile < NTILE_; tile++) {
        const int base = tile * KT_;
        // store prefetched tile
        *reinterpret_cast<float4*>(&ktile[kk0 * KSTR_ + k40 * 4]) = pre0;
        *reinterpret_cast<float4*>(&ktile[kk1 * KSTR_ + k41 * 4]) = pre1;
        __syncthreads();
        // prefetch next tile (overlaps compute)
        if (tile + 1 < NTILE_) {
            const int nb = base + KT_;
            int s0 = nb + kk0, s1 = nb + kk1;
            const float* p0 = (s0 < N_) ? kbase + (size_t)s0 * HD_ + k40 * 4
                            : (s0 < S_) ? mem_k + (h * M_ + (s0 - N_)) * HD_ + k40 * 4
                                        : kbase + k40 * 4;
            const float* p1 = (s1 < N_) ? kbase + (size_t)s1 * HD_ + k41 * 4
                            : (s1 < S_) ? mem_k + (h * M_ + (s1 - N_)) * HD_ + k41 * 4
                                        : kbase + k41 * 4;
            pre0 = *reinterpret_cast<const float4*>(p0);
            pre1 = *reinterpret_cast<const float4*>(p1);
        }
        // compute: 1 key x 4 queries, packed f32x2
        ull a0 = 0ull, a1 = 0ull, a2 = 0ull, a3 = 0ull;
        const float* kr = &ktile[key * KSTR_];
#pragma unroll
        for (int j = 0; j < 8; j++) {
            float4 kv = *reinterpret_cast<const float4*>(kr + j * 4);
            ull k01 = pk2(kv.x, kv.y), k23 = pk2(kv.z, kv.w);
            float4 q0 = *reinterpret_cast<const float4*>(&qsh[(qbase + 0) * 32 + j * 4]);
            float4 q1 = *reinterpret_cast<const float4*>(&qsh[(qbase + 1) * 32 + j * 4]);
            float4 q2 = *reinterpret_cast<const float4*>(&qsh[(qbase + 2) * 32 + j * 4]);
            float4 q3 = *reinterpret_cast<const float4*>(&qsh[(qbase + 3) * 32 + j * 4]);
            fma2(a0, pk2(q0.x, q0.y), k01); fma2(a0, pk2(q0.z, q0.w), k23);
            fma2(a1, pk2(q1.x, q1.y), k01); fma2(a1, pk2(q1.z, q1.w), k23);
            fma2(a2, pk2(q2.x, q2.y), k01); fma2(a2, pk2(q2.z, q2.w), k23);
            fma2(a3, pk2(q3.x, q3.y), k01); fma2(a3, pk2(q3.z, q3.w), k23);
        }
        const int s = base + key;
        if (s < S_) {
            float r0 = upk_sum(a0) * sfac;
            float r1 = upk_sum(a1) * sfac;
            float r2 = upk_sum(a2) * sfac;
            float r3 = upk_sum(a3) * sfac;
            if (s == n0 + qbase + 0) r0 = -FLT_MAX;
            if (s == n0 + qbase + 1) r1 = -FLT_MAX;
            if (s == n0 + qbase + 2) r2 = -FLT_MAX;
            if (s == n0 + qbase + 3) r3 = -FLT_MAX;
            sc[(qbase + 0) * SP_ + s] = r0;
            sc[(qbase + 1) * SP_ + s] = r1;
            sc[(qbase + 2) * SP_ + s] = r2;
            sc[(qbase + 3) * SP_ + s] = r3;
        }
        __syncthreads();
    }

    // ---------- Phase 2: one warp per query ----------
    const int wid  = tid >> 5;              // query index 0..15
    const int lane = tid & 31;
    float* row = sc + wid * SP_;

    // streaming exact top-32: one element per lane
    float my = row[lane];                   // chunk 0 (always full)
    float curmin = warp_min(my);
    float vn = row[32 + lane];              // prefetch chunk 1
    for (int it = 1; it <= 64; it++) {
        float v = vn;
        {   // prefetch next
            int sn = (it + 1) * 32 + lane;
            vn = (sn < S_) ? row[sn] : -FLT_MAX;
        }
        unsigned cand = __ballot_sync(0xffffffffu, v > curmin);
        while (cand) {
            int l = __ffs(cand) - 1;
            cand &= cand - 1;
            float cv = __shfl_sync(0xffffffffu, v, l);
            if (cv > curmin) {
                unsigned mb = __ballot_sync(0xffffffffu, my == curmin);
                if (lane == __ffs(mb) - 1) my = cv;
                curmin = warp_min(my);
            }
        }
    }
    const float thr = curmin;               // exact 32nd-largest value

    // survivor compaction + softmax numerator (shift by thr)
    int* bi   = (int*)(ktile) + wid * 288;          // idx  [0..135]
    float* bw = ktile + wid * 288 + 144;            // wght [0..135]
    int cnt = 0;
    float lsum = 0.f;
    for (int it = 0; it < 65; it++) {
        int s = it * 32 + lane;
        bool p = false; float w = 0.f;
        if (s < S_) {
            float v = row[s];
            if (v >= thr) { p = true; w = __expf(v - thr); }
        }
        unsigned m = __ballot_sync(0xffffffffu, p);
        if (m) {
            int pos = cnt + __popc(m & ((1u << lane) - 1u));
            if (p && pos < AVCAP_) { bi[pos] = s; bw[pos] = w; }
            cnt += __popc(m);
        }
        lsum += w;
    }
#pragma unroll
    for (int o = 16; o; o >>= 1) lsum += __shfl_xor_sync(0xffffffffu, lsum, o);
    const float wsum = lsum;

    float acc = 0.f;
    if (cnt <= AVCAP_) {
        // pad to multiple of 8 with harmless (idx 0, weight 0)
        int cntp = (cnt + 7) & ~7;
        if (lane == 0)
            for (int j = cnt; j < cntp; j++) { bi[j] = 0; bw[j] = 0.f; }
        __syncwarp();
        for (int i = 0; i < cntp; i += 8) {
#pragma unroll
            for (int u = 0; u < 8; u++) {
                int s = bi[i + u];
                float w = bw[i + u];
                const float* vp = (s < N_) ? (vbase + (size_t)s * HD_)
                                           : (mem_v + (h * M_ + (s - N_)) * HD_);
                acc += w * vp[lane];
            }
        }
    } else {
        // rare tie-overflow fallback: serial ballot walk (always correct)
        for (int s0 = 0; s0 < S_; s0 += 32) {
            int s = s0 + lane;
            bool p = false; float w = 0.f;
            if (s < S_) {
                float v = row[s];
                if (v >= thr) { p = true; w = __expf(v - thr); }
            }
            unsigned m = __ballot_sync(0xffffffffu, p);
            while (m) {
                int l = __ffs(m) - 1;
                m &= m - 1;
                int ss = s0 + l;
                float ww = __shfl_sync(0xffffffffu, w, l);
                const float* vp = (ss < N_) ? (vbase + (size_t)ss * HD_)
                                            : (mem_v + (h * M_ + (ss - N_)) * HD_);
                acc += ww * vp[lane];
            }
        }
    }
    g_attn[((size_t)(b * N_ + n0 + wid)) * (H_ * HD_) + h * HD_ + lane] = acc / wsum;
}

// =====================================================================
// GEMM 2: out = g_attn @ w_proj + b_proj.  [8192,256] x [256,256]
// =====================================================================
__global__ __launch_bounds__(256) void gemm_proj_kernel(
    const float* __restrict__ W, const float* __restrict__ bias,
    float* __restrict__ out)
{
    __shared__ __align__(16) float As[16 * 132];
    __shared__ __align__(16) float Bs[16 * 128];
    const int tid = threadIdx.x;
    const int rowBase = blockIdx.y * 128;
    const int colBase = blockIdx.x * 128;
    const int ty = tid >> 4, tx = tid & 15;

    float acc[8][8];
#pragma unroll
    for (int i = 0; i < 8; i++)
#pragma unroll
        for (int j = 0; j < 8; j++) acc[i][j] = 0.f;

    for (int kb = 0; kb < 256; kb += 16) {
#pragma unroll
        for (int i = 0; i < 2; i++) {
            int f4 = tid + i * 256;
            int row = f4 >> 2;
            int kc = (f4 & 3) << 2;
            float4 v = *reinterpret_cast<const float4*>(
                g_attn + (size_t)(rowBase + row) * 256 + kb + kc);
            As[(kc + 0) * 132 + row] = v.x;
            As[(kc + 1) * 132 + row] = v.y;
            As[(kc + 2) * 132 + row] = v.z;
            As[(kc + 3) * 132 + row] = v.w;
        }
#pragma unroll
        for (int i = 0; i < 2; i++) {
            int f4 = tid + i * 256;
            int kr = f4 >> 5;
            int cc = (f4 & 31) << 2;
            *reinterpret_cast<float4*>(&Bs[kr * 128 + cc]) =
                *reinterpret_cast<const float4*>(
                    W + (size_t)(kb + kr) * 256 + colBase + cc);
        }
        __syncthreads();
#pragma unroll
        for (int kk = 0; kk < 16; kk++) {
            float a[8], b[8];
            *reinterpret_cast<float4*>(&a[0]) =
                *reinterpret_cast<const float4*>(&As[kk * 132 + ty * 8]);
            *reinterpret_cast<float4*>(&a[4]) =
                *reinterpret_cast<const float4*>(&As[kk * 132 + ty * 8 + 4]);
            *reinterpret_cast<float4*>(&b[0]) =
                *reinterpret_cast<const float4*>(&Bs[kk * 128 + tx * 8]);
            *reinterpret_cast<float4*>(&b[4]) =
                *reinterpret_cast<const float4*>(&Bs[kk * 128 + tx * 8 + 4]);
#pragma unroll
            for (int i = 0; i < 8; i++)
#pragma unroll
                for (int j = 0; j < 8; j++) acc[i][j] += a[i] * b[j];
        }
        __syncthreads();
    }

#pragma unroll
    for (int i = 0; i < 8; i++) {
        int r = rowBase + ty * 8 + i;
#pragma unroll
        for (int j = 0; j < 8; j++) {
            int c = colBase + tx * 8 + j;
            out[(size_t)r * 256 + c] = acc[i][j] + bias[c];
        }
    }
}

// =====================================================================
extern "C" void kernel_launch(void* const* d_in, const int* in_sizes, int n_in,
                              void* d_out, int out_size)
{
    const float* x      = (const float*)d_in[0];
    const float* w_qkv  = (const float*)d_in[1];
    const float* b_qkv  = (const float*)d_in[2];
    const float* w_proj = (const float*)d_in[3];
    const float* b_proj = (const float*)d_in[4];
    const float* scale  = (const float*)d_in[5];
    const float* mem_k  = (const float*)d_in[6];
    const float* mem_v  = (const float*)d_in[7];
    float* out = (float*)d_out;

    dim3 g1(768 / 128, ROWS_ / 128);
    gemm_qkv_kernel<<<g1, 256>>>(x, w_qkv, b_qkv);

    const int smem_bytes = (QT_ * SP_ + QT_ * 32 + KT_ * KSTR_) * 4;
    static int attr_set = 0;
    if (!attr_set) {
        cudaFuncSetAttribute(attn_kernel,
                             cudaFuncAttributeMaxDynamicSharedMemorySize, smem_bytes);
        attr_set = 1;
    }
    attn_kernel<<<B_ * H_ * (N_ / QT_), 512, smem_bytes>>>(scale, mem_k, mem_v);

    dim3 g3(256 / 128, ROWS_ / 128);
    gemm_proj_kernel<<<g3, 256>>>(w_proj, b_proj, out);
}

// round 10
// speedup vs baseline: 2.0020x; 1.6946x over previous
#include <cuda_runtime.h>
#include <float.h>
#include <stdint.h>

#define B_   4
#define N_   2048
#define DIM_ 256
#define H_   8
#define HD_  32
#define M_   4
#define S_   2052          // N + M
#define TOPK_ 32
#define ROWS_ (B_*N_)      // 8192

#define QT_    16          // queries per block (attention)
#define CH_    512         // keys per staged chunk
#define NCH_   4           // 2048 / CH_
#define KTSTR_ 521         // kt row stride (floats): conflict-free
#define SP_    2052        // score row stride (floats)
#define AVCAP_ 128

typedef unsigned long long ull;

// ---------------- scratch (no cudaMalloc allowed) ----------------
__device__ float g_q[B_*H_*N_*HD_];      // 8 MB
__device__ float g_k[B_*H_*N_*HD_];      // 8 MB
__device__ float g_v[B_*H_*N_*HD_];      // 8 MB
__device__ float g_attn[B_*N_*H_*HD_];   // 8 MB  [B,N,H*HD]

__device__ __forceinline__ ull pk2(float a, float b) {
    ull r; asm("mov.b64 %0, {%1,%2};" : "=l"(r) : "f"(a), "f"(b)); return r;
}
__device__ __forceinline__ void fma2(ull& d, ull a, ull b) {
    asm("fma.rn.f32x2 %0, %1, %2, %0;" : "+l"(d) : "l"(a), "l"(b));
}
__device__ __forceinline__ void upk(ull a, float& lo, float& hi) {
    asm("mov.b64 {%0,%1}, %2;" : "=f"(lo), "=f"(hi) : "l"(a));
}
// monotonic float<->uint (order-preserving, bijective)
__device__ __forceinline__ unsigned enc_f(float f) {
    unsigned u = __float_as_uint(f);
    return u ^ (((unsigned)((int)u >> 31)) | 0x80000000u);
}
__device__ __forceinline__ float dec_f(unsigned e) {
    unsigned u = e ^ (((unsigned)((int)(~e) >> 31)) | 0x80000000u);
    return __uint_as_float(u);
}

// =====================================================================
// GEMM 1: qkv = x @ w_qkv + b_qkv, scattered into g_q/g_k/g_v [B,H,N,HD]
// =====================================================================
__global__ __launch_bounds__(256) void gemm_qkv_kernel(
    const float* __restrict__ X, const float* __restrict__ W,
    const float* __restrict__ bias)
{
    __shared__ __align__(16) float As[16 * 132];   // [k][m], padded
    __shared__ __align__(16) float Bs[16 * 128];   // [k][n]
    const int tid = threadIdx.x;
    const int rowBase = blockIdx.y * 128;
    const int colBase = blockIdx.x * 128;
    const int ty = tid >> 4, tx = tid & 15;

    float acc[8][8];
#pragma unroll
    for (int i = 0; i < 8; i++)
#pragma unroll
        for (int j = 0; j < 8; j++) acc[i][j] = 0.f;

    for (int kb = 0; kb < DIM_; kb += 16) {
#pragma unroll
        for (int i = 0; i < 2; i++) {
            int f4 = tid + i * 256;
            int row = f4 >> 2;
            int kc = (f4 & 3) << 2;
            float4 v = *reinterpret_cast<const float4*>(
                X + (size_t)(rowBase + row) * DIM_ + kb + kc);
            As[(kc + 0) * 132 + row] = v.x;
            As[(kc + 1) * 132 + row] = v.y;
            As[(kc + 2) * 132 + row] = v.z;
            As[(kc + 3) * 132 + row] = v.w;
        }
#pragma unroll
        for (int i = 0; i < 2; i++) {
            int f4 = tid + i * 256;
            int kr = f4 >> 5;
            int cc = (f4 & 31) << 2;
            *reinterpret_cast<float4*>(&Bs[kr * 128 + cc]) =
                *reinterpret_cast<const float4*>(
                    W + (size_t)(kb + kr) * 768 + colBase + cc);
        }
        __syncthreads();
#pragma unroll
        for (int kk = 0; kk < 16; kk++) {
            float a[8], b[8];
            *reinterpret_cast<float4*>(&a[0]) =
                *reinterpret_cast<const float4*>(&As[kk * 132 + ty * 8]);
            *reinterpret_cast<float4*>(&a[4]) =
                *reinterpret_cast<const float4*>(&As[kk * 132 + ty * 8 + 4]);
            *reinterpret_cast<float4*>(&b[0]) =
                *reinterpret_cast<const float4*>(&Bs[kk * 128 + tx * 8]);
            *reinterpret_cast<float4*>(&b[4]) =
                *reinterpret_cast<const float4*>(&Bs[kk * 128 + tx * 8 + 4]);
#pragma unroll
            for (int i = 0; i < 8; i++)
#pragma unroll
                for (int j = 0; j < 8; j++) acc[i][j] += a[i] * b[j];
        }
        __syncthreads();
    }

#pragma unroll
    for (int i = 0; i < 8; i++) {
        int r = rowBase + ty * 8 + i;
        int bb = r >> 11;
        int n = r & (N_ - 1);
#pragma unroll
        for (int j = 0; j < 8; j++) {
            int c = colBase + tx * 8 + j;
            float val = acc[i][j] + bias[c];
            int t = c >> 8;
            int h = (c >> 5) & 7;
            int d = c & 31;
            float* dst = (t == 0) ? g_q : (t == 1) ? g_k : g_v;
            dst[(((size_t)(bb * H_ + h)) * N_ + n) * HD_ + d] = val;
        }
    }
}

// =====================================================================
// Attention: one block = 16 queries of one (b,h). 512 threads, 16 warps.
// Phase 1: lane = 1 key x 16 queries; K transposed in smem (conflict-free
//          scalar reads), q transposed (broadcast LDS.128), packed fma2.
// Phase 2: warp per query: seeded streaming exact top-32 with REDUX.MIN
//          on monotone-encoded keys -> compaction -> batched sparse AV.
// =====================================================================
__global__ __launch_bounds__(512, 1) void attn_kernel(
    const float* __restrict__ scale,
    const float* __restrict__ mem_k,
    const float* __restrict__ mem_v)
{
    extern __shared__ __align__(16) float smem[];
    float* sc  = smem;                   // [16][2052]   131328 B
    float* qts = sc + QT_ * SP_;         // [32][16]       2048 B (q transposed)
    float* kt  = qts + 512;              // [32][KTSTR_]  66688 B (K transposed)

    const int tid = threadIdx.x;
    const int bid = blockIdx.x;
    const int qt = bid & 127;            // N_/QT_ = 128 tiles
    const int h  = (bid >> 7) & (H_ - 1);
    const int b  = bid >> 10;
    const int n0 = qt * QT_;

    const float sfac = 0.17677669529663687f * scale[h];
    const float* kbase = g_k + ((size_t)(b * H_ + h)) * N_ * HD_;
    const float* vbase = g_v + ((size_t)(b * H_ + h)) * N_ * HD_;

    // load q transposed: qts[d][qi]
    {
        const float* qb = g_q + (((size_t)(b * H_ + h)) * N_ + n0) * HD_;
        int qi = tid >> 5, d = tid & 31;
        qts[d * QT_ + qi] = qb[qi * HD_ + d];
    }

    const int w = tid >> 5, lane = tid & 31;
    const int keyloc = w * 32 + lane;            // key within chunk (0..511)

    // staging geometry: 4096 float4 per 512-key chunk / 512 thr = 8 each
    // item i: key = key0 + i*64, float4-within-key = d4
    const int key0 = tid >> 3;                   // 0..63
    const int d4   = tid & 7;
    float4 pre[8];
#pragma unroll
    for (int i = 0; i < 8; i++)
        pre[i] = *reinterpret_cast<const float4*>(
            kbase + (size_t)(key0 + i * 64) * HD_ + d4 * 4);

    // ---------- Phase 1: scores for keys 0..2047 ----------
    for (int c = 0; c < NCH_; c++) {
        const int cbase = c * CH_;
        // store prefetched chunk transposed (conflict-free)
#pragma unroll
        for (int i = 0; i < 8; i++) {
            int key = key0 + i * 64;
            kt[(d4 * 4 + 0) * KTSTR_ + key] = pre[i].x;
            kt[(d4 * 4 + 1) * KTSTR_ + key] = pre[i].y;
            kt[(d4 * 4 + 2) * KTSTR_ + key] = pre[i].z;
            kt[(d4 * 4 + 3) * KTSTR_ + key] = pre[i].w;
        }
        __syncthreads();
        if (c + 1 < NCH_) {
            const int nb = cbase + CH_;
#pragma unroll
            for (int i = 0; i < 8; i++)
                pre[i] = *reinterpret_cast<const float4*>(
                    kbase + (size_t)(nb + key0 + i * 64) * HD_ + d4 * 4);
        }

        ull acc[8];
#pragma unroll
        for (int p = 0; p < 8; p++) acc[p] = 0ull;

#pragma unroll 8
        for (int d = 0; d < 32; d++) {
            float kd = kt[d * KTSTR_ + keyloc];
            ull kk = pk2(kd, kd);
            const float* qrow = qts + d * QT_;
#pragma unroll
            for (int j = 0; j < 4; j++) {
                float4 qv = *reinterpret_cast<const float4*>(qrow + j * 4);
                fma2(acc[2 * j + 0], pk2(qv.x, qv.y), kk);
                fma2(acc[2 * j + 1], pk2(qv.z, qv.w), kk);
            }
        }
        const int key = cbase + keyloc;
#pragma unroll
        for (int p = 0; p < 8; p++) {
            float lo, hi; upk(acc[p], lo, hi);
            float r0 = lo * sfac, r1 = hi * sfac;
            if (key == n0 + 2 * p)     r0 = -FLT_MAX;
            if (key == n0 + 2 * p + 1) r1 = -FLT_MAX;
            sc[(2 * p + 0) * SP_ + key] = r0;
            sc[(2 * p + 1) * SP_ + key] = r1;
        }
        __syncthreads();
    }

    // ---------- memory keys: warp w computes query w x 4 mem keys ----------
    {
        float qv = qts[lane * QT_ + w];          // q[w][lane(=d)]
#pragma unroll
        for (int mk = 0; mk < M_; mk++) {
            float kv = mem_k[(h * M_ + mk) * HD_ + lane];
            float p = qv * kv;
#pragma unroll
            for (int o = 16; o; o >>= 1) p += __shfl_xor_sync(0xffffffffu, p, o);
            if (lane == 0) sc[w * SP_ + N_ + mk] = p * sfac;  // never diagonal
        }
        __syncwarp();
    }

    // ---------- Phase 2: one warp per query (query = w) ----------
    float* row = sc + w * SP_;

    // pass A: per-lane max (encoded) + its index
    unsigned mu = 0u; int mi = -1;
    for (int it = 0; it < 65; it++) {
        int s = it * 32 + lane;
        if (s < S_) {
            unsigned vu = enc_f(row[s]);
            if (vu > mu) { mu = vu; mi = s; }
        }
    }
    unsigned myu = mu;                                   // seeded candidate set
    unsigned curmin = __reduce_min_sync(0xffffffffu, myu);

    // pass B: stream, insert v > curmin (excluding each lane's seeded max)
    for (int it = 0; it < 65; it++) {
        int s = it * 32 + lane;
        unsigned vu = (s < S_) ? enc_f(row[s]) : 0u;
        bool cnd = (vu > curmin) && (s != mi);
        unsigned cand = __ballot_sync(0xffffffffu, cnd);
        while (cand) {
            int l = __ffs(cand) - 1;
            cand &= cand - 1;
            unsigned cv = __shfl_sync(0xffffffffu, vu, l);
            if (cv > curmin) {
                unsigned mb = __ballot_sync(0xffffffffu, myu == curmin);
                if (lane == __ffs(mb) - 1) myu = cv;
                curmin = __reduce_min_sync(0xffffffffu, myu);
            }
        }
    }
    const unsigned thr_u = curmin;           // exact 32nd-largest (encoded)
    const float thr = dec_f(thr_u);

    // ---------- compaction + softmax numerator (shift by thr) ----------
    int*   bi = (int*)kt + w * 288;          // reuse kt (phase 1 done)
    float* bw = kt + w * 288 + 144;
    int cnt = 0;
    float lsum = 0.f;
    for (int it = 0; it < 65; it++) {
        int s = it * 32 + lane;
        bool p = false; float wv = 0.f;
        if (s < S_) {
            float v = row[s];
            if (enc_f(v) >= thr_u) { p = true; wv = __expf(v - thr); }
        }
        unsigned m = __ballot_sync(0xffffffffu, p);
        if (m) {
            int pos = cnt + __popc(m & ((1u << lane) - 1u));
            if (p && pos < AVCAP_) { bi[pos] = s; bw[pos] = wv; }
            cnt += __popc(m);
        }
        lsum += wv;
    }
#pragma unroll
    for (int o = 16; o; o >>= 1) lsum += __shfl_xor_sync(0xffffffffu, lsum, o);
    const float wsum = lsum;

    float acc = 0.f;
    if (cnt <= AVCAP_) {
        int cntp = (cnt + 7) & ~7;
        if (lane == 0)
            for (int j = cnt; j < cntp; j++) { bi[j] = 0; bw[j] = 0.f; }
        __syncwarp();
        for (int i = 0; i < cntp; i += 8) {
#pragma unroll
            for (int u = 0; u < 8; u++) {
                int s = bi[i + u];
                float wv = bw[i + u];
                const float* vp = (s < N_) ? (vbase + (size_t)s * HD_)
                                           : (mem_v + (h * M_ + (s - N_)) * HD_);
                acc += wv * vp[lane];
            }
        }
    } else {
        // rare tie-overflow fallback: serial ballot walk (always correct)
        for (int s0 = 0; s0 < S_; s0 += 32) {
            int s = s0 + lane;
            bool p = false; float wv = 0.f;
            if (s < S_) {
                float v = row[s];
                if (enc_f(v) >= thr_u) { p = true; wv = __expf(v - thr); }
            }
            unsigned m = __ballot_sync(0xffffffffu, p);
            while (m) {
                int l = __ffs(m) - 1;
                m &= m - 1;
                int ss = s0 + l;
                float ww = __shfl_sync(0xffffffffu, wv, l);
                const float* vp = (ss < N_) ? (vbase + (size_t)ss * HD_)
                                            : (mem_v + (h * M_ + (ss - N_)) * HD_);
                acc += ww * vp[lane];
            }
        }
    }
    g_attn[((size_t)(b * N_ + n0 + w)) * (H_ * HD_) + h * HD_ + lane] = acc / wsum;
}

// =====================================================================
// GEMM 2: out = g_attn @ w_proj + b_proj.  [8192,256] x [256,256]
// =====================================================================
__global__ __launch_bounds__(256) void gemm_proj_kernel(
    const float* __restrict__ W, const float* __restrict__ bias,
    float* __restrict__ out)
{
    __shared__ __align__(16) float As[16 * 132];
    __shared__ __align__(16) float Bs[16 * 128];
    const int tid = threadIdx.x;
    const int rowBase = blockIdx.y * 128;
    const int colBase = blockIdx.x * 128;
    const int ty = tid >> 4, tx = tid & 15;

    float acc[8][8];
#pragma unroll
    for (int i = 0; i < 8; i++)
#pragma unroll
        for (int j = 0; j < 8; j++) acc[i][j] = 0.f;

    for (int kb = 0; kb < 256; kb += 16) {
#pragma unroll
        for (int i = 0; i < 2; i++) {
            int f4 = tid + i * 256;
            int row = f4 >> 2;
            int kc = (f4 & 3) << 2;
            float4 v = *reinterpret_cast<const float4*>(
                g_attn + (size_t)(rowBase + row) * 256 + kb + kc);
            As[(kc + 0) * 132 + row] = v.x;
            As[(kc + 1) * 132 + row] = v.y;
            As[(kc + 2) * 132 + row] = v.z;
            As[(kc + 3) * 132 + row] = v.w;
        }
#pragma unroll
        for (int i = 0; i < 2; i++) {
            int f4 = tid + i * 256;
            int kr = f4 >> 5;
            int cc = (f4 & 31) << 2;
            *reinterpret_cast<float4*>(&Bs[kr * 128 + cc]) =
                *reinterpret_cast<const float4*>(
                    W + (size_t)(kb + kr) * 256 + colBase + cc);
        }
        __syncthreads();
#pragma unroll
        for (int kk = 0; kk < 16; kk++) {
            float a[8], b[8];
            *reinterpret_cast<float4*>(&a[0]) =
                *reinterpret_cast<const float4*>(&As[kk * 132 + ty * 8]);
            *reinterpret_cast<float4*>(&a[4]) =
                *reinterpret_cast<const float4*>(&As[kk * 132 + ty * 8 + 4]);
            *reinterpret_cast<float4*>(&b[0]) =
                *reinterpret_cast<const float4*>(&Bs[kk * 128 + tx * 8]);
            *reinterpret_cast<float4*>(&b[4]) =
                *reinterpret_cast<const float4*>(&Bs[kk * 128 + tx * 8 + 4]);
#pragma unroll
            for (int i = 0; i < 8; i++)
#pragma unroll
                for (int j = 0; j < 8; j++) acc[i][j] += a[i] * b[j];
        }
        __syncthreads();
    }

#pragma unroll
    for (int i = 0; i < 8; i++) {
        int r = rowBase + ty * 8 + i;
#pragma unroll
        for (int j = 0; j < 8; j++) {
            int c = colBase + tx * 8 + j;
            out[(size_t)r * 256 + c] = acc[i][j] + bias[c];
        }
    }
}

// =====================================================================
extern "C" void kernel_launch(void* const* d_in, const int* in_sizes, int n_in,
                              void* d_out, int out_size)
{
    const float* x      = (const float*)d_in[0];
    const float* w_qkv  = (const float*)d_in[1];
    const float* b_qkv  = (const float*)d_in[2];
    const float* w_proj = (const float*)d_in[3];
    const float* b_proj = (const float*)d_in[4];
    const float* scale  = (const float*)d_in[5];
    const float* mem_k  = (const float*)d_in[6];
    const float* mem_v  = (const float*)d_in[7];
    float* out = (float*)d_out;

    dim3 g1(768 / 128, ROWS_ / 128);
    gemm_qkv_kernel<<<g1, 256>>>(x, w_qkv, b_qkv);

    const int smem_bytes = (QT_ * SP_ + 512 + 32 * KTSTR_) * 4;   // 200064 B
    static int attr_set = 0;
    if (!attr_set) {
        cudaFuncSetAttribute(attn_kernel,
                             cudaFuncAttributeMaxDynamicSharedMemorySize, smem_bytes);
        attr_set = 1;
    }
    attn_kernel<<<B_ * H_ * (N_ / QT_), 512, smem_bytes>>>(scale, mem_k, mem_v);

    dim3 g3(256 / 128, ROWS_ / 128);
    gemm_proj_kernel<<<g3, 256>>>(w_proj, b_proj, out);
}

// round 15
// speedup vs baseline: 2.6020x; 1.2997x over previous
#include <cuda_runtime.h>
#include <float.h>
#include <stdint.h>

#define B_   4
#define N_   2048
#define DIM_ 256
#define H_   8
#define HD_  32
#define M_   4
#define S_   2052          // N + M
#define TOPK_ 32
#define ROWS_ (B_*N_)      // 8192 (proj GEMM rows)
#define SROWS_ (B_*H_*N_)  // 65536 (score rows)
#define SP2_  2048         // g_s row stride (floats) — mem-key tail in smem
#define SSTR_ 2056         // smem row stride (floats), 16B-aligned
#define AVCAP_ 160

typedef unsigned long long ull;

// ---------------- scratch (no cudaMalloc allowed) ----------------
__device__ float g_q[B_*H_*N_*HD_];      // 8 MB
__device__ float g_k[B_*H_*N_*HD_];      // 8 MB
__device__ float g_v[B_*H_*N_*HD_];      // 8 MB
__device__ float g_attn[B_*N_*H_*HD_];   // 8 MB  [B,N,H*HD]
__device__ float g_s[(size_t)SROWS_ * SP2_ + 64];  // 512 MB scores

__device__ __forceinline__ ull pk2(float a, float b) {
    ull r; asm("mov.b64 %0, {%1,%2};" : "=l"(r) : "f"(a), "f"(b)); return r;
}
__device__ __forceinline__ void fma2(ull& d, ull a, ull b) {
    asm("fma.rn.f32x2 %0, %1, %2, %0;" : "+l"(d) : "l"(a), "l"(b));
}
__device__ __forceinline__ void upk(ull a, float& lo, float& hi) {
    asm("mov.b64 {%0,%1}, %2;" : "=f"(lo), "=f"(hi) : "l"(a));
}
// monotonic float<->uint (order-preserving, bijective)
__device__ __forceinline__ unsigned enc_f(float f) {
    unsigned u = __float_as_uint(f);
    return u ^ (((unsigned)((int)u >> 31)) | 0x80000000u);
}
__device__ __forceinline__ float dec_f(unsigned e) {
    unsigned u = e ^ (((unsigned)((int)(~e) >> 31)) | 0x80000000u);
    return __uint_as_float(u);
}

// =====================================================================
// GEMM 1: qkv = x @ w_qkv + b_qkv, scattered into g_q/g_k/g_v [B,H,N,HD]
// =====================================================================
__global__ __launch_bounds__(256) void gemm_qkv_kernel(
    const float* __restrict__ X, const float* __restrict__ W,
    const float* __restrict__ bias)
{
    __shared__ __align__(16) float As[16 * 132];
    __shared__ __align__(16) float Bs[16 * 128];
    const int tid = threadIdx.x;
    const int rowBase = blockIdx.y * 128;
    const int colBase = blockIdx.x * 128;
    const int ty = tid >> 4, tx = tid & 15;

    float acc[8][8];
#pragma unroll
    for (int i = 0; i < 8; i++)
#pragma unroll
        for (int j = 0; j < 8; j++) acc[i][j] = 0.f;

    for (int kb = 0; kb < DIM_; kb += 16) {
#pragma unroll
        for (int i = 0; i < 2; i++) {
            int f4 = tid + i * 256;
            int row = f4 >> 2;
            int kc = (f4 & 3) << 2;
            float4 v = *reinterpret_cast<const float4*>(
                X + (size_t)(rowBase + row) * DIM_ + kb + kc);
            As[(kc + 0) * 132 + row] = v.x;
            As[(kc + 1) * 132 + row] = v.y;
            As[(kc + 2) * 132 + row] = v.z;
            As[(kc + 3) * 132 + row] = v.w;
        }
#pragma unroll
        for (int i = 0; i < 2; i++) {
            int f4 = tid + i * 256;
            int kr = f4 >> 5;
            int cc = (f4 & 31) << 2;
            *reinterpret_cast<float4*>(&Bs[kr * 128 + cc]) =
                *reinterpret_cast<const float4*>(
                    W + (size_t)(kb + kr) * 768 + colBase + cc);
        }
        __syncthreads();
#pragma unroll
        for (int kk = 0; kk < 16; kk++) {
            float a[8], b[8];
            *reinterpret_cast<float4*>(&a[0]) =
                *reinterpret_cast<const float4*>(&As[kk * 132 + ty * 8]);
            *reinterpret_cast<float4*>(&a[4]) =
                *reinterpret_cast<const float4*>(&As[kk * 132 + ty * 8 + 4]);
            *reinterpret_cast<float4*>(&b[0]) =
                *reinterpret_cast<const float4*>(&Bs[kk * 128 + tx * 8]);
            *reinterpret_cast<float4*>(&b[4]) =
                *reinterpret_cast<const float4*>(&Bs[kk * 128 + tx * 8 + 4]);
#pragma unroll
            for (int i = 0; i < 8; i++)
#pragma unroll
                for (int j = 0; j < 8; j++) acc[i][j] += a[i] * b[j];
        }
        __syncthreads();
    }

#pragma unroll
    for (int i = 0; i < 8; i++) {
        int r = rowBase + ty * 8 + i;
        int bb = r >> 11;
        int n = r & (N_ - 1);
#pragma unroll
        for (int j = 0; j < 8; j++) {
            int c = colBase + tx * 8 + j;
            float val = acc[i][j] + bias[c];
            int t = c >> 8;
            int h = (c >> 5) & 7;
            int d = c & 31;
            float* dst = (t == 0) ? g_q : (t == 1) ? g_k : g_v;
            dst[(((size_t)(bb * H_ + h)) * N_ + n) * HD_ + d] = val;
        }
    }
}

// =====================================================================
// Score GEMM: one block = 64 queries x 256 keys of one (b,h), K=32.
// Q staged d-major (stride 68, LDS.128 broadcast = pre-packed f32x2),
// K staged d-major (stride 257 odd, conflict-free scalar LDS).
// acc: 4 query-pairs x 8 keys in packed f32x2. Scores -> g_s [bh*N+q][k].
// =====================================================================
__global__ __launch_bounds__(256, 2) void score_kernel(
    const float* __restrict__ scale)
{
    __shared__ __align__(16) float qs[32 * 68];    //  8.7 KB [d][q]
    __shared__ __align__(16) float ks[32 * 257];   // 32.9 KB [d][key]

    const int tid = threadIdx.x;
    const int kb = blockIdx.x * 256;
    const int qb = blockIdx.y * 64;
    const int bh = blockIdx.z;                     // 0..31
    const int h  = bh & 7;
    const float sfac = 0.17677669529663687f * scale[h];

    const float* kbase = g_k + ((size_t)bh * N_ + kb) * HD_;
    const float* qbase = g_q + ((size_t)bh * N_ + qb) * HD_;

    // stage Q (64 rows): coalesced LDG, transposed scalar STS
#pragma unroll
    for (int i = 0; i < 2; i++) {
        int f4 = tid + i * 256;
        int r = f4 >> 3, d4 = f4 & 7;
        float4 v = *reinterpret_cast<const float4*>(qbase + r * HD_ + d4 * 4);
        qs[(d4 * 4 + 0) * 68 + r] = v.x;
        qs[(d4 * 4 + 1) * 68 + r] = v.y;
        qs[(d4 * 4 + 2) * 68 + r] = v.z;
        qs[(d4 * 4 + 3) * 68 + r] = v.w;
    }
    // stage K (256 rows): coalesced LDG, conflict-free transposed STS
#pragma unroll
    for (int i = 0; i < 8; i++) {
        int f4 = tid + i * 256;
        int r = f4 >> 3, d4 = f4 & 7;
        float4 v = *reinterpret_cast<const float4*>(kbase + r * HD_ + d4 * 4);
        ks[(d4 * 4 + 0) * 257 + r] = v.x;
        ks[(d4 * 4 + 1) * 257 + r] = v.y;
        ks[(d4 * 4 + 2) * 257 + r] = v.z;
        ks[(d4 * 4 + 3) * 257 + r] = v.w;
    }
    __syncthreads();

    const int ty = tid >> 5;     // query octet: queries qb + ty*8 .. +7
    const int tx = tid & 31;     // key lane: keys kb + tx + 32u

    ull acc[4][8];
#pragma unroll
    for (int p = 0; p < 4; p++)
#pragma unroll
        for (int u = 0; u < 8; u++) acc[p][u] = 0ull;

#pragma unroll 8
    for (int d = 0; d < 32; d++) {
        const float* qrow = qs + d * 68 + ty * 8;
        longlong2 qa = *reinterpret_cast<const longlong2*>(qrow);
        longlong2 qb2 = *reinterpret_cast<const longlong2*>(qrow + 4);
        const float* krow = ks + d * 257 + tx;
#pragma unroll
        for (int u = 0; u < 8; u++) {
            float kv = krow[u * 32];
            ull kk = pk2(kv, kv);
            fma2(acc[0][u], (ull)qa.x,  kk);
            fma2(acc[1][u], (ull)qa.y,  kk);
            fma2(acc[2][u], (ull)qb2.x, kk);
            fma2(acc[3][u], (ull)qb2.y, kk);
        }
    }

    // epilogue: scale + diag mask + coalesced scalar stores
#pragma unroll
    for (int p = 0; p < 4; p++) {
        const int gq0 = qb + ty * 8 + 2 * p;
        float* r0 = g_s + ((size_t)bh * N_ + gq0) * SP2_ + kb + tx;
        float* r1 = r0 + SP2_;
#pragma unroll
        for (int u = 0; u < 8; u++) {
            float lo, hi; upk(acc[p][u], lo, hi);
            lo *= sfac; hi *= sfac;
            const int gk = kb + tx + u * 32;
            if (gk == gq0)     lo = -FLT_MAX;
            if (gk == gq0 + 1) hi = -FLT_MAX;
            r0[u * 32] = lo;
            r1[u * 32] = hi;
        }
    }
}

// =====================================================================
// Selection: 128 thr = 4 warps, one (b,h,n) score row per warp.
// Row staged to smem once (coalesced LDG.128); mem-key scores computed
// into the smem tail; exact seeded streaming top-32 (REDUX.MIN);
// compaction; batched sparse AV.
// =====================================================================
__global__ __launch_bounds__(128) void select_kernel(
    const float* __restrict__ scale,
    const float* __restrict__ mem_k,
    const float* __restrict__ mem_v)
{
    __shared__ __align__(16) float srows[4 * SSTR_];   // 32.9 KB
    __shared__ int   sbi[4][AVCAP_ + 8];
    __shared__ float sbw[4][AVCAP_ + 8];

    const int w = threadIdx.x >> 5, lane = threadIdx.x & 31;
    const int sidx = blockIdx.x * 4 + w;          // 0..65535 (b,h,n)
    const int bh = sidx >> 11;                    // 0..31
    const int n  = sidx & (N_ - 1);
    const int h  = bh & 7;
    const int b  = bh >> 3;
    const float sfac = 0.17677669529663687f * scale[h];
    const float* grow = g_s + (size_t)sidx * SP2_;
    const float* vbase = g_v + (size_t)bh * N_ * HD_;
    float* srow = srows + w * SSTR_;

    // ---- stage row into smem (512 float4, coalesced) ----
    {
        const float4* g4 = reinterpret_cast<const float4*>(grow);
        float4* s4 = reinterpret_cast<float4*>(srow);
#pragma unroll
        for (int it = 0; it < 16; it++)
            s4[it * 32 + lane] = g4[it * 32 + lane];
    }
    // ---- mem-key scores -> smem tail (cols 2048..2051) ----
    {
        float qd = g_q[(size_t)sidx * HD_ + lane];
#pragma unroll
        for (int mk = 0; mk < M_; mk++) {
            float p = qd * mem_k[(h * M_ + mk) * HD_ + lane];
#pragma unroll
            for (int o = 16; o; o >>= 1) p += __shfl_xor_sync(0xffffffffu, p, o);
            if (lane == mk) srow[N_ + mk] = p * sfac;   // never the diagonal
        }
        __syncwarp();
    }

    // ---- pass A: per-lane max + index (seeds) ----
    unsigned mu = 0u; int mi = -1;
    for (int it = 0; it < 65; it++) {
        int s = it * 32 + lane;
        if (s < S_) {
            unsigned vu = enc_f(srow[s]);
            if (vu > mu) { mu = vu; mi = s; }
        }
    }
    unsigned myu = mu;
    unsigned curmin = __reduce_min_sync(0xffffffffu, myu);

    // ---- pass B: stream, insert encoded v > curmin (excl. seeds) ----
    for (int it = 0; it < 65; it++) {
        int s = it * 32 + lane;
        unsigned vu = 0u;
        if (s < S_) vu = enc_f(srow[s]);
        bool cnd = (vu > curmin) && (s != mi);
        unsigned cand = __ballot_sync(0xffffffffu, cnd);
        while (cand) {
            int l = __ffs(cand) - 1;
            cand &= cand - 1;
            unsigned cv = __shfl_sync(0xffffffffu, vu, l);
            if (cv > curmin) {
                unsigned mb = __ballot_sync(0xffffffffu, myu == curmin);
                if (lane == __ffs(mb) - 1) myu = cv;
                curmin = __reduce_min_sync(0xffffffffu, myu);
            }
        }
    }
    const unsigned thr_u = curmin;            // exact 32nd-largest (encoded)
    const float thr = dec_f(thr_u);

    // ---- compaction + softmax numerator (shift by thr) ----
    int*   bi = sbi[w];
    float* bw = sbw[w];
    int cnt = 0;
    float lsum = 0.f;
    for (int it = 0; it < 65; it++) {
        int s = it * 32 + lane;
        bool p = false; float wv = 0.f;
        if (s < S_) {
            float v = srow[s];
            if (enc_f(v) >= thr_u) { p = true; wv = __expf(v - thr); }
        }
        unsigned m = __ballot_sync(0xffffffffu, p);
        if (m) {
            int pos = cnt + __popc(m & ((1u << lane) - 1u));
            if (p && pos < AVCAP_) { bi[pos] = s; bw[pos] = wv; }
            cnt += __popc(m);
        }
        lsum += wv;
    }
#pragma unroll
    for (int o = 16; o; o >>= 1) lsum += __shfl_xor_sync(0xffffffffu, lsum, o);
    const float wsum = lsum;

    // ---- batched sparse AV ----
    float acc = 0.f;
    if (cnt <= AVCAP_) {
        int cntp = (cnt + 7) & ~7;
        if (lane == 0)
            for (int j = cnt; j < cntp; j++) { bi[j] = 0; bw[j] = 0.f; }
        __syncwarp();
        for (int i = 0; i < cntp; i += 8) {
#pragma unroll
            for (int u = 0; u < 8; u++) {
                int s = bi[i + u];
                float wv = bw[i + u];
                const float* vp = (s < N_) ? (vbase + (size_t)s * HD_)
                                           : (mem_v + (h * M_ + (s - N_)) * HD_);
                acc += wv * vp[lane];
            }
        }
    } else {
        // rare tie-overflow fallback: serial ballot walk (always correct)
        for (int it = 0; it < 65; it++) {
            int s = it * 32 + lane;
            bool p = false; float wv = 0.f;
            if (s < S_) {
                float v = srow[s];
                if (enc_f(v) >= thr_u) { p = true; wv = __expf(v - thr); }
            }
            unsigned m = __ballot_sync(0xffffffffu, p);
            while (m) {
                int l = __ffs(m) - 1;
                m &= m - 1;
                int ss = it * 32 + l;
                float ww = __shfl_sync(0xffffffffu, wv, l);
                const float* vp = (ss < N_) ? (vbase + (size_t)ss * HD_)
                                            : (mem_v + (h * M_ + (ss - N_)) * HD_);
                acc += ww * vp[lane];
            }
        }
    }
    g_attn[((size_t)(b * N_ + n)) * (H_ * HD_) + h * HD_ + lane] = acc / wsum;
}

// =====================================================================
// GEMM 2: out = g_attn @ w_proj + b_proj.  [8192,256] x [256,256]
// =====================================================================
__global__ __launch_bounds__(256) void gemm_proj_kernel(
    const float* __restrict__ W, const float* __restrict__ bias,
    float* __restrict__ out)
{
    __shared__ __align__(16) float As[16 * 132];
    __shared__ __align__(16) float Bs[16 * 128];
    const int tid = threadIdx.x;
    const int rowBase = blockIdx.y * 128;
    const int colBase = blockIdx.x * 128;
    const int ty = tid >> 4, tx = tid & 15;

    float acc[8][8];
#pragma unroll
    for (int i = 0; i < 8; i++)
#pragma unroll
        for (int j = 0; j < 8; j++) acc[i][j] = 0.f;

    for (int kb = 0; kb < 256; kb += 16) {
#pragma unroll
        for (int i = 0; i < 2; i++) {
            int f4 = tid + i * 256;
            int row = f4 >> 2;
            int kc = (f4 & 3) << 2;
            float4 v = *reinterpret_cast<const float4*>(
                g_attn + (size_t)(rowBase + row) * 256 + kb + kc);
            As[(kc + 0) * 132 + row] = v.x;
            As[(kc + 1) * 132 + row] = v.y;
            As[(kc + 2) * 132 + row] = v.z;
            As[(kc + 3) * 132 + row] = v.w;
        }
#pragma unroll
        for (int i = 0; i < 2; i++) {
            int f4 = tid + i * 256;
            int kr = f4 >> 5;
            int cc = (f4 & 31) << 2;
            *reinterpret_cast<float4*>(&Bs[kr * 128 + cc]) =
                *reinterpret_cast<const float4*>(
                    W + (size_t)(kb + kr) * 256 + colBase + cc);
        }
        __syncthreads();
#pragma unroll
        for (int kk = 0; kk < 16; kk++) {
            float a[8], b[8];
            *reinterpret_cast<float4*>(&a[0]) =
                *reinterpret_cast<const float4*>(&As[kk * 132 + ty * 8]);
            *reinterpret_cast<float4*>(&a[4]) =
                *reinterpret_cast<const float4*>(&As[kk * 132 + ty * 8 + 4]);
            *reinterpret_cast<float4*>(&b[0]) =
                *reinterpret_cast<const float4*>(&Bs[kk * 128 + tx * 8]);
            *reinterpret_cast<float4*>(&b[4]) =
                *reinterpret_cast<const float4*>(&Bs[kk * 128 + tx * 8 + 4]);
#pragma unroll
            for (int i = 0; i < 8; i++)
#pragma unroll
                for (int j = 0; j < 8; j++) acc[i][j] += a[i] * b[j];
        }
        __syncthreads();
    }

#pragma unroll
    for (int i = 0; i < 8; i++) {
        int r = rowBase + ty * 8 + i;
#pragma unroll
        for (int j = 0; j < 8; j++) {
            int c = colBase + tx * 8 + j;
            out[(size_t)r * 256 + c] = acc[i][j] + bias[c];
        }
    }
}

// =====================================================================
extern "C" void kernel_launch(void* const* d_in, const int* in_sizes, int n_in,
                              void* d_out, int out_size)
{
    const float* x      = (const float*)d_in[0];
    const float* w_qkv  = (const float*)d_in[1];
    const float* b_qkv  = (const float*)d_in[2];
    const float* w_proj = (const float*)d_in[3];
    const float* b_proj = (const float*)d_in[4];
    const float* scale  = (const float*)d_in[5];
    const float* mem_k  = (const float*)d_in[6];
    const float* mem_v  = (const float*)d_in[7];
    float* out = (float*)d_out;

    dim3 g1(768 / 128, ROWS_ / 128);
    gemm_qkv_kernel<<<g1, 256>>>(x, w_qkv, b_qkv);

    dim3 gs(N_ / 256, N_ / 64, B_ * H_);          // 8 x 32 x 32
    score_kernel<<<gs, 256>>>(scale);

    select_kernel<<<SROWS_ / 4, 128>>>(scale, mem_k, mem_v);

    dim3 g3(256 / 128, ROWS_ / 128);
    gemm_proj_kernel<<<g3, 256>>>(w_proj, b_proj, out);
}

// round 17
// speedup vs baseline: 2.7240x; 1.0469x over previous
#include <cuda_runtime.h>
#include <float.h>
#include <stdint.h>

#define B_   4
#define N_   2048
#define DIM_ 256
#define H_   8
#define HD_  32
#define M_   4
#define S_   2052          // N + M
#define TOPK_ 32
#define ROWS_ (B_*N_)      // 8192 (proj GEMM rows)
#define SROWS_ (B_*H_*N_)  // 65536 (score rows)
#define SP2_  2048         // g_s row stride (floats) — mem-key tail in smem
#define SSTR_ 2056         // smem row stride (floats), 16B-aligned
#define CAND_ 256          // candidate buffer per row
#define AVCAP_ 160

typedef unsigned long long ull;

// ---------------- scratch (no cudaMalloc allowed) ----------------
__device__ float g_q[B_*H_*N_*HD_];      // 8 MB
__device__ float g_k[B_*H_*N_*HD_];      // 8 MB
__device__ float g_v[B_*H_*N_*HD_];      // 8 MB
__device__ float g_attn[B_*N_*H_*HD_];   // 8 MB  [B,N,H*HD]
__device__ float g_s[(size_t)SROWS_ * SP2_ + 64];  // 512 MB scores

__device__ __forceinline__ ull pk2(float a, float b) {
    ull r; asm("mov.b64 %0, {%1,%2};" : "=l"(r) : "f"(a), "f"(b)); return r;
}
__device__ __forceinline__ void fma2(ull& d, ull a, ull b) {
    asm("fma.rn.f32x2 %0, %1, %2, %0;" : "+l"(d) : "l"(a), "l"(b));
}
__device__ __forceinline__ void upk(ull a, float& lo, float& hi) {
    asm("mov.b64 {%0,%1}, %2;" : "=f"(lo), "=f"(hi) : "l"(a));
}
// monotonic float<->uint (order-preserving, bijective)
__device__ __forceinline__ unsigned enc_f(float f) {
    unsigned u = __float_as_uint(f);
    return u ^ (((unsigned)((int)u >> 31)) | 0x80000000u);
}
__device__ __forceinline__ float dec_f(unsigned e) {
    unsigned u = e ^ (((unsigned)((int)(~e) >> 31)) | 0x80000000u);
    return __uint_as_float(u);
}

// =====================================================================
// GEMM 1: qkv = x @ w_qkv + b_qkv, scattered into g_q/g_k/g_v [B,H,N,HD]
// 128x128 tile, BK=16, 8x8 micro in packed f32x2.
// =====================================================================
__global__ __launch_bounds__(256) void gemm_qkv_kernel(
    const float* __restrict__ X, const float* __restrict__ W,
    const float* __restrict__ bias)
{
    __shared__ __align__(16) float As[16 * 132];
    __shared__ __align__(16) float Bs[16 * 128];
    const int tid = threadIdx.x;
    const int rowBase = blockIdx.y * 128;
    const int colBase = blockIdx.x * 128;
    const int ty = tid >> 4, tx = tid & 15;

    ull acc2[8][4];
#pragma unroll
    for (int i = 0; i < 8; i++)
#pragma unroll
        for (int j = 0; j < 4; j++) acc2[i][j] = 0ull;

    for (int kb = 0; kb < DIM_; kb += 16) {
#pragma unroll
        for (int i = 0; i < 2; i++) {
            int f4 = tid + i * 256;
            int row = f4 >> 2;
            int kc = (f4 & 3) << 2;
            float4 v = *reinterpret_cast<const float4*>(
                X + (size_t)(rowBase + row) * DIM_ + kb + kc);
            As[(kc + 0) * 132 + row] = v.x;
            As[(kc + 1) * 132 + row] = v.y;
            As[(kc + 2) * 132 + row] = v.z;
            As[(kc + 3) * 132 + row] = v.w;
        }
#pragma unroll
        for (int i = 0; i < 2; i++) {
            int f4 = tid + i * 256;
            int kr = f4 >> 5;
            int cc = (f4 & 31) << 2;
            *reinterpret_cast<float4*>(&Bs[kr * 128 + cc]) =
                *reinterpret_cast<const float4*>(
                    W + (size_t)(kb + kr) * 768 + colBase + cc);
        }
        __syncthreads();
#pragma unroll
        for (int kk = 0; kk < 16; kk++) {
            float a[8];
            *reinterpret_cast<float4*>(&a[0]) =
                *reinterpret_cast<const float4*>(&As[kk * 132 + ty * 8]);
            *reinterpret_cast<float4*>(&a[4]) =
                *reinterpret_cast<const float4*>(&As[kk * 132 + ty * 8 + 4]);
            longlong2 lb0 = *reinterpret_cast<const longlong2*>(&Bs[kk * 128 + tx * 8]);
            longlong2 lb1 = *reinterpret_cast<const longlong2*>(&Bs[kk * 128 + tx * 8 + 4]);
#pragma unroll
            for (int i = 0; i < 8; i++) {
                ull ai = pk2(a[i], a[i]);
                fma2(acc2[i][0], ai, (ull)lb0.x);
                fma2(acc2[i][1], ai, (ull)lb0.y);
                fma2(acc2[i][2], ai, (ull)lb1.x);
                fma2(acc2[i][3], ai, (ull)lb1.y);
            }
        }
        __syncthreads();
    }

#pragma unroll
    for (int i = 0; i < 8; i++) {
        int r = rowBase + ty * 8 + i;
        int bb = r >> 11;
        int n = r & (N_ - 1);
#pragma unroll
        for (int j2 = 0; j2 < 4; j2++) {
            float lo, hi; upk(acc2[i][j2], lo, hi);
#pragma unroll
            for (int e = 0; e < 2; e++) {
                int c = colBase + tx * 8 + 2 * j2 + e;
                float val = (e ? hi : lo) + bias[c];
                int t = c >> 8;
                int h = (c >> 5) & 7;
                int d = c & 31;
                float* dst = (t == 0) ? g_q : (t == 1) ? g_k : g_v;
                dst[(((size_t)(bb * H_ + h)) * N_ + n) * HD_ + d] = val;
            }
        }
    }
}

// =====================================================================
// Score GEMM: one block = 64 queries x 256 keys of one (b,h), K=32.
// =====================================================================
__global__ __launch_bounds__(256, 2) void score_kernel(
    const float* __restrict__ scale)
{
    __shared__ __align__(16) float qs[32 * 68];    //  8.7 KB [d][q]
    __shared__ __align__(16) float ks[32 * 257];   // 32.9 KB [d][key]

    const int tid = threadIdx.x;
    const int kb = blockIdx.x * 256;
    const int qb = blockIdx.y * 64;
    const int bh = blockIdx.z;                     // 0..31
    const int h  = bh & 7;
    const float sfac = 0.17677669529663687f * scale[h];

    const float* kbase = g_k + ((size_t)bh * N_ + kb) * HD_;
    const float* qbase = g_q + ((size_t)bh * N_ + qb) * HD_;

#pragma unroll
    for (int i = 0; i < 2; i++) {
        int f4 = tid + i * 256;
        int r = f4 >> 3, d4 = f4 & 7;
        float4 v = *reinterpret_cast<const float4*>(qbase + r * HD_ + d4 * 4);
        qs[(d4 * 4 + 0) * 68 + r] = v.x;
        qs[(d4 * 4 + 1) * 68 + r] = v.y;
        qs[(d4 * 4 + 2) * 68 + r] = v.z;
        qs[(d4 * 4 + 3) * 68 + r] = v.w;
    }
#pragma unroll
    for (int i = 0; i < 8; i++) {
        int f4 = tid + i * 256;
        int r = f4 >> 3, d4 = f4 & 7;
        float4 v = *reinterpret_cast<const float4*>(kbase + r * HD_ + d4 * 4);
        ks[(d4 * 4 + 0) * 257 + r] = v.x;
        ks[(d4 * 4 + 1) * 257 + r] = v.y;
        ks[(d4 * 4 + 2) * 257 + r] = v.z;
        ks[(d4 * 4 + 3) * 257 + r] = v.w;
    }
    __syncthreads();

    const int ty = tid >> 5;
    const int tx = tid & 31;

    ull acc[4][8];
#pragma unroll
    for (int p = 0; p < 4; p++)
#pragma unroll
        for (int u = 0; u < 8; u++) acc[p][u] = 0ull;

#pragma unroll 8
    for (int d = 0; d < 32; d++) {
        const float* qrow = qs + d * 68 + ty * 8;
        longlong2 qa = *reinterpret_cast<const longlong2*>(qrow);
        longlong2 qb2 = *reinterpret_cast<const longlong2*>(qrow + 4);
        const float* krow = ks + d * 257 + tx;
#pragma unroll
        for (int u = 0; u < 8; u++) {
            float kv = krow[u * 32];
            ull kk = pk2(kv, kv);
            fma2(acc[0][u], (ull)qa.x,  kk);
            fma2(acc[1][u], (ull)qa.y,  kk);
            fma2(acc[2][u], (ull)qb2.x, kk);
            fma2(acc[3][u], (ull)qb2.y, kk);
        }
    }

#pragma unroll
    for (int p = 0; p < 4; p++) {
        const int gq0 = qb + ty * 8 + 2 * p;
        float* r0 = g_s + ((size_t)bh * N_ + gq0) * SP2_ + kb + tx;
        float* r1 = r0 + SP2_;
#pragma unroll
        for (int u = 0; u < 8; u++) {
            float lo, hi; upk(acc[p][u], lo, hi);
            lo *= sfac; hi *= sfac;
            const int gk = kb + tx + u * 32;
            if (gk == gq0)     lo = -FLT_MAX;
            if (gk == gq0 + 1) hi = -FLT_MAX;
            r0[u * 32] = lo;
            r1[u * 32] = hi;
        }
    }
}

// =====================================================================
// Selection: 128 thr = 4 warps, one (b,h,n) score row per warp.
// Stage row + lane max fused; t0 = REDUX_MIN(lane maxima); compact
// candidates (>= t0) once; exact 32nd via 32x extract-max (REDUX.MAX).
// Fallback (cnt > CAND_): R15's proven strided-partition streaming
// (per-lane max recomputed over the SAME partition pass B uses).
// =====================================================================
__global__ __launch_bounds__(128) void select_kernel(
    const float* __restrict__ scale,
    const float* __restrict__ mem_k,
    const float* __restrict__ mem_v)
{
    __shared__ __align__(16) float srows[4 * SSTR_];   // 32.9 KB
    __shared__ int   cidx[4][CAND_];                   // 4 KB
    __shared__ float cvalb[4][CAND_];                  // 4 KB
    __shared__ int   sbi[4][AVCAP_ + 8];
    __shared__ float sbw[4][AVCAP_ + 8];

    const int w = threadIdx.x >> 5, lane = threadIdx.x & 31;
    const int sidx = blockIdx.x * 4 + w;          // 0..65535 (b,h,n)
    const int bh = sidx >> 11;
    const int n  = sidx & (N_ - 1);
    const int h  = bh & 7;
    const int b  = bh >> 3;
    const float sfac = 0.17677669529663687f * scale[h];
    const float* grow = g_s + (size_t)sidx * SP2_;
    const float* vbase = g_v + (size_t)bh * N_ * HD_;
    float* srow = srows + w * SSTR_;

    // ---- stage row + per-lane max (fused; for t0 only) ----
    unsigned mu = 0u;
    {
        const float4* g4 = reinterpret_cast<const float4*>(grow);
        float4* s4 = reinterpret_cast<float4*>(srow);
#pragma unroll
        for (int it = 0; it < 16; it++) {
            float4 v = g4[it * 32 + lane];
            s4[it * 32 + lane] = v;
            unsigned e;
            e = enc_f(v.x); mu = max(mu, e);
            e = enc_f(v.y); mu = max(mu, e);
            e = enc_f(v.z); mu = max(mu, e);
            e = enc_f(v.w); mu = max(mu, e);
        }
    }
    // ---- mem-key scores -> smem tail (cols 2048..2051) ----
    {
        float qd = g_q[(size_t)sidx * HD_ + lane];
#pragma unroll
        for (int mk = 0; mk < M_; mk++) {
            float p = qd * mem_k[(h * M_ + mk) * HD_ + lane];
#pragma unroll
            for (int o = 16; o; o >>= 1) p += __shfl_xor_sync(0xffffffffu, p, o);
            if (lane == mk) srow[N_ + mk] = p * sfac;   // never the diagonal
        }
    }
    __syncwarp();

    const unsigned t0 = __reduce_min_sync(0xffffffffu, mu);

    // ---- candidate compaction: all values with enc >= t0 ----
    int cnt = 0;
    for (int it = 0; it < 65; it++) {
        int s = it * 32 + lane;
        bool p = false; float v = 0.f;
        if (s < S_) {
            v = srow[s];
            p = (enc_f(v) >= t0);
        }
        unsigned m = __ballot_sync(0xffffffffu, p);
        if (m) {
            int pos = cnt + __popc(m & ((1u << lane) - 1u));
            if (p && pos < CAND_) { cidx[w][pos] = s; cvalb[w][pos] = v; }
            cnt += __popc(m);
        }
    }
    __syncwarp();

    unsigned thr_u;
    if (cnt <= CAND_) {
        // ---- exact 32nd largest via 32x extract-max over candidates ----
        unsigned c[8];
#pragma unroll
        for (int r = 0; r < 8; r++) {
            int i = r * 32 + lane;
            c[r] = (i < cnt) ? enc_f(cvalb[w][i]) : 0u;
        }
        unsigned lm = 0u;
#pragma unroll
        for (int r = 0; r < 8; r++) lm = max(lm, c[r]);
        thr_u = 0u;
        for (int k = 0; k < TOPK_; k++) {
            unsigned mx = __reduce_max_sync(0xffffffffu, lm);
            thr_u = mx;
            if (k < TOPK_ - 1) {
                unsigned bal = __ballot_sync(0xffffffffu, lm == mx);
                if (lane == __ffs(bal) - 1) {
                    bool cl = false;
#pragma unroll
                    for (int r = 0; r < 8; r++)
                        if (!cl && c[r] == mx) { c[r] = 0u; cl = true; }
                    lm = 0u;
#pragma unroll
                    for (int r = 0; r < 8; r++) lm = max(lm, c[r]);
                }
            }
        }
    } else {
        // ---- rare fallback: strided-partition seed + streaming insert
        //      (R15's proven exact path; seeds and stream use the SAME
        //       partition so the seed exclusion is checked by its owner) ----
        unsigned mu2 = 0u; int mi2 = -1;
        for (int it = 0; it < 65; it++) {
            int s = it * 32 + lane;
            if (s < S_) {
                unsigned vu = enc_f(srow[s]);
                if (vu > mu2) { mu2 = vu; mi2 = s; }
            }
        }
        unsigned myu = mu2;
        unsigned curmin = __reduce_min_sync(0xffffffffu, myu);
        for (int it = 0; it < 65; it++) {
            int s = it * 32 + lane;
            unsigned vu = 0u;
            if (s < S_) vu = enc_f(srow[s]);
            bool cnd = (vu > curmin) && (s != mi2);
            unsigned cand = __ballot_sync(0xffffffffu, cnd);
            while (cand) {
                int l = __ffs(cand) - 1;
                cand &= cand - 1;
                unsigned cv = __shfl_sync(0xffffffffu, vu, l);
                if (cv > curmin) {
                    unsigned mb = __ballot_sync(0xffffffffu, myu == curmin);
                    if (lane == __ffs(mb) - 1) myu = cv;
                    curmin = __reduce_min_sync(0xffffffffu, myu);
                }
            }
        }
        thr_u = curmin;
    }
    const float thr = dec_f(thr_u);

    // ---- survivors + weights ----
    int*   bi = sbi[w];
    float* bw = sbw[w];
    int scnt = 0;
    float lsum = 0.f;
    if (cnt <= CAND_) {
        // survivors are a subset of the candidate buffer
        for (int i0 = 0; i0 < cnt; i0 += 32) {
            int i = i0 + lane;
            bool p = false; float wv = 0.f; int si = 0;
            if (i < cnt) {
                float v = cvalb[w][i];
                si = cidx[w][i];
                if (enc_f(v) >= thr_u) { p = true; wv = __expf(v - thr); }
            }
            unsigned m = __ballot_sync(0xffffffffu, p);
            if (m) {
                int pos = scnt + __popc(m & ((1u << lane) - 1u));
                if (p && pos < AVCAP_) { bi[pos] = si; bw[pos] = wv; }
                scnt += __popc(m);
            }
            lsum += wv;
        }
    } else {
        for (int it = 0; it < 65; it++) {
            int s = it * 32 + lane;
            bool p = false; float wv = 0.f;
            if (s < S_) {
                float v = srow[s];
                if (enc_f(v) >= thr_u) { p = true; wv = __expf(v - thr); }
            }
            unsigned m = __ballot_sync(0xffffffffu, p);
            if (m) {
                int pos = scnt + __popc(m & ((1u << lane) - 1u));
                if (p && pos < AVCAP_) { bi[pos] = s; bw[pos] = wv; }
                scnt += __popc(m);
            }
            lsum += wv;
        }
    }
#pragma unroll
    for (int o = 16; o; o >>= 1) lsum += __shfl_xor_sync(0xffffffffu, lsum, o);
    const float wsum = lsum;
    __syncwarp();

    // ---- batched sparse AV ----
    float acc = 0.f;
    if (scnt <= AVCAP_) {
        int cntp = (scnt + 7) & ~7;
        if (lane == 0)
            for (int j = scnt; j < cntp; j++) { bi[j] = 0; bw[j] = 0.f; }
        __syncwarp();
        for (int i = 0; i < cntp; i += 8) {
#pragma unroll
            for (int u = 0; u < 8; u++) {
                int s = bi[i + u];
                float wv = bw[i + u];
                const float* vp = (s < N_) ? (vbase + (size_t)s * HD_)
                                           : (mem_v + (h * M_ + (s - N_)) * HD_);
                acc += wv * vp[lane];
            }
        }
    } else {
        // extreme tie-overflow: serial ballot walk over full row
        for (int it = 0; it < 65; it++) {
            int s = it * 32 + lane;
            bool p = false; float wv = 0.f;
            if (s < S_) {
                float v = srow[s];
                if (enc_f(v) >= thr_u) { p = true; wv = __expf(v - thr); }
            }
            unsigned m = __ballot_sync(0xffffffffu, p);
            while (m) {
                int l = __ffs(m) - 1;
                m &= m - 1;
                int ss = it * 32 + l;
                float ww = __shfl_sync(0xffffffffu, wv, l);
                const float* vp = (ss < N_) ? (vbase + (size_t)ss * HD_)
                                            : (mem_v + (h * M_ + (ss - N_)) * HD_);
                acc += ww * vp[lane];
            }
        }
    }
    g_attn[((size_t)(b * N_ + n)) * (H_ * HD_) + h * HD_ + lane] = acc / wsum;
}

// =====================================================================
// GEMM 2: out = g_attn @ w_proj + b_proj.  [8192,256] x [256,256]
// 8x8 micro in packed f32x2.
// =====================================================================
__global__ __launch_bounds__(256) void gemm_proj_kernel(
    const float* __restrict__ W, const float* __restrict__ bias,
    float* __restrict__ out)
{
    __shared__ __align__(16) float As[16 * 132];
    __shared__ __align__(16) float Bs[16 * 128];
    const int tid = threadIdx.x;
    const int rowBase = blockIdx.y * 128;
    const int colBase = blockIdx.x * 128;
    const int ty = tid >> 4, tx = tid & 15;

    ull acc2[8][4];
#pragma unroll
    for (int i = 0; i < 8; i++)
#pragma unroll
        for (int j = 0; j < 4; j++) acc2[i][j] = 0ull;

    for (int kb = 0; kb < 256; kb += 16) {
#pragma unroll
        for (int i = 0; i < 2; i++) {
            int f4 = tid + i * 256;
            int row = f4 >> 2;
            int kc = (f4 & 3) << 2;
            float4 v = *reinterpret_cast<const float4*>(
                g_attn + (size_t)(rowBase + row) * 256 + kb + kc);
            As[(kc + 0) * 132 + row] = v.x;
            As[(kc + 1) * 132 + row] = v.y;
            As[(kc + 2) * 132 + row] = v.z;
            As[(kc + 3) * 132 + row] = v.w;
        }
#pragma unroll
        for (int i = 0; i < 2; i++) {
            int f4 = tid + i * 256;
            int kr = f4 >> 5;
            int cc = (f4 & 31) << 2;
            *reinterpret_cast<float4*>(&Bs[kr * 128 + cc]) =
                *reinterpret_cast<const float4*>(
                    W + (size_t)(kb + kr) * 256 + colBase + cc);
        }
        __syncthreads();
#pragma unroll
        for (int kk = 0; kk < 16; kk++) {
            float a[8];
            *reinterpret_cast<float4*>(&a[0]) =
                *reinterpret_cast<const float4*>(&As[kk * 132 + ty * 8]);
            *reinterpret_cast<float4*>(&a[4]) =
                *reinterpret_cast<const float4*>(&As[kk * 132 + ty * 8 + 4]);
            longlong2 lb0 = *reinterpret_cast<const longlong2*>(&Bs[kk * 128 + tx * 8]);
            longlong2 lb1 = *reinterpret_cast<const longlong2*>(&Bs[kk * 128 + tx * 8 + 4]);
#pragma unroll
            for (int i = 0; i < 8; i++) {
                ull ai = pk2(a[i], a[i]);
                fma2(acc2[i][0], ai, (ull)lb0.x);
                fma2(acc2[i][1], ai, (ull)lb0.y);
                fma2(acc2[i][2], ai, (ull)lb1.x);
                fma2(acc2[i][3], ai, (ull)lb1.y);
            }
        }
        __syncthreads();
    }

#pragma unroll
    for (int i = 0; i < 8; i++) {
        int r = rowBase + ty * 8 + i;
#pragma unroll
        for (int j2 = 0; j2 < 4; j2++) {
            float lo, hi; upk(acc2[i][j2], lo, hi);
            int c = colBase + tx * 8 + 2 * j2;
            out[(size_t)r * 256 + c]     = lo + bias[c];
            out[(size_t)r * 256 + c + 1] = hi + bias[c + 1];
        }
    }
}

// =====================================================================
extern "C" void kernel_launch(void* const* d_in, const int* in_sizes, int n_in,
                              void* d_out, int out_size)
{
    const float* x      = (const float*)d_in[0];
    const float* w_qkv  = (const float*)d_in[1];
    const float* b_qkv  = (const float*)d_in[2];
    const float* w_proj = (const float*)d_in[3];
    const float* b_proj = (const float*)d_in[4];
    const float* scale  = (const float*)d_in[5];
    const float* mem_k  = (const float*)d_in[6];
    const float* mem_v  = (const float*)d_in[7];
    float* out = (float*)d_out;

    dim3 g1(768 / 128, ROWS_ / 128);
    gemm_qkv_kernel<<<g1, 256>>>(x, w_qkv, b_qkv);

    dim3 gs(N_ / 256, N_ / 64, B_ * H_);          // 8 x 32 x 32
    score_kernel<<<gs, 256>>>(scale);

    select_kernel<<<SROWS_ / 4, 128>>>(scale, mem_k, mem_v);

    dim3 g3(256 / 128, ROWS_ / 128);
    gemm_proj_kernel<<<g3, 256>>>(w_proj, b_proj, out);
}